// round 2
// baseline (speedup 1.0000x reference)
#include <cuda_runtime.h>
#include <math.h>

#define S_LEN   2048
#define BATCH   2
#define DMODEL  1024
#define NHEADS  16
#define DK      64
#define DFF     4096
#define MTOK    (BATCH * S_LEN)   // 4096 tokens

// ---------------- scratch (device globals; no allocations allowed) ----------
__device__ float g_q   [MTOK * DMODEL];
__device__ float g_k   [MTOK * DMODEL];
__device__ float g_v   [MTOK * DMODEL];
__device__ float g_attn[MTOK * DMODEL];
__device__ float g_proj[MTOK * DMODEL];
__device__ float g_x1  [MTOK * DMODEL];
__device__ float g_ff  [MTOK * DFF];

// ---------------- GEMM: C[M,N] = A[M,K] * B[N,K]^T ---------------------------
// 64x64 tile, BK=16, 256 threads, 4x4 outputs/thread.
__global__ void gemm_nt_kernel(const float* __restrict__ A,
                               const float* __restrict__ B,
                               float* __restrict__ C,
                               int M, int N, int K) {
    __shared__ float As[64][17];
    __shared__ float Bs[64][17];

    const int tid = threadIdx.x;
    const int tx  = tid & 15;        // 0..15 -> 4 output cols
    const int ty  = tid >> 4;        // 0..15 -> 4 output rows
    const int row0 = blockIdx.y * 64;
    const int col0 = blockIdx.x * 64;

    float acc[4][4] = {};

    const int lr = tid >> 2;             // 0..63 tile row for loading
    const int lk = (tid & 3) << 2;       // 0,4,8,12 k-offset (float4)

    for (int k0 = 0; k0 < K; k0 += 16) {
        float4 a4 = *(const float4*)(A + (size_t)(row0 + lr) * K + k0 + lk);
        float4 b4 = *(const float4*)(B + (size_t)(col0 + lr) * K + k0 + lk);
        As[lr][lk + 0] = a4.x; As[lr][lk + 1] = a4.y;
        As[lr][lk + 2] = a4.z; As[lr][lk + 3] = a4.w;
        Bs[lr][lk + 0] = b4.x; Bs[lr][lk + 1] = b4.y;
        Bs[lr][lk + 2] = b4.z; Bs[lr][lk + 3] = b4.w;
        __syncthreads();

        #pragma unroll
        for (int kk = 0; kk < 16; kk++) {
            float a[4], b[4];
            #pragma unroll
            for (int m = 0; m < 4; m++) a[m] = As[4 * ty + m][kk];
            #pragma unroll
            for (int n = 0; n < 4; n++) b[n] = Bs[4 * tx + n][kk];
            #pragma unroll
            for (int m = 0; m < 4; m++)
                #pragma unroll
                for (int n = 0; n < 4; n++)
                    acc[m][n] = fmaf(a[m], b[n], acc[m][n]);
        }
        __syncthreads();
    }

    #pragma unroll
    for (int m = 0; m < 4; m++) {
        float* crow = C + (size_t)(row0 + 4 * ty + m) * N + col0 + 4 * tx;
        #pragma unroll
        for (int n = 0; n < 4; n++) crow[n] = acc[m][n];
    }
}

// ---------------- Flash attention (per (b,h), 64-query tiles) ----------------
// Q/K/V/O laid out [B*S, DMODEL] with head h at column h*64 (concat-heads
// layout, so no transposes are ever needed).
#define FLD 65   // smem leading dim (bank-conflict pad)

__global__ void flash_attn_kernel(const float* __restrict__ Q,
                                  const float* __restrict__ K,
                                  const float* __restrict__ V,
                                  float* __restrict__ O) {
    extern __shared__ float sm[];
    float* Qs = sm;                  // [64][FLD]
    float* Ks = Qs + 64 * FLD;       // [64][FLD]  (re-used as P after S compute)
    float* Vs = Ks + 64 * FLD;       // [64][FLD]

    const int tid = threadIdx.x;
    const int tx  = tid & 15;
    const int ty  = tid >> 4;
    const int q0  = blockIdx.x * 64;
    const int h   = blockIdx.y;
    const int b   = blockIdx.z;
    const size_t base = (size_t)b * S_LEN * DMODEL + (size_t)h * DK;

    // load Q tile (64 rows x 64 cols)
    for (int i = tid; i < 64 * 16; i += 256) {
        int rr = i >> 4, cc = (i & 15) << 2;
        float4 v4 = *(const float4*)(Q + base + (size_t)(q0 + rr) * DMODEL + cc);
        Qs[rr * FLD + cc + 0] = v4.x; Qs[rr * FLD + cc + 1] = v4.y;
        Qs[rr * FLD + cc + 2] = v4.z; Qs[rr * FLD + cc + 3] = v4.w;
    }

    float mrow[4], lrow[4], o[4][4];
    #pragma unroll
    for (int i = 0; i < 4; i++) {
        mrow[i] = -1e30f; lrow[i] = 0.f;
        #pragma unroll
        for (int n = 0; n < 4; n++) o[i][n] = 0.f;
    }
    __syncthreads();

    for (int kt = 0; kt < S_LEN; kt += 64) {
        // load K and V tiles
        for (int i = tid; i < 64 * 16; i += 256) {
            int rr = i >> 4, cc = (i & 15) << 2;
            float4 k4 = *(const float4*)(K + base + (size_t)(kt + rr) * DMODEL + cc);
            float4 v4 = *(const float4*)(V + base + (size_t)(kt + rr) * DMODEL + cc);
            Ks[rr * FLD + cc + 0] = k4.x; Ks[rr * FLD + cc + 1] = k4.y;
            Ks[rr * FLD + cc + 2] = k4.z; Ks[rr * FLD + cc + 3] = k4.w;
            Vs[rr * FLD + cc + 0] = v4.x; Vs[rr * FLD + cc + 1] = v4.y;
            Vs[rr * FLD + cc + 2] = v4.z; Vs[rr * FLD + cc + 3] = v4.w;
        }
        __syncthreads();

        // S = Q * K^T * scale   (each thread: 4x4 of the 64x64 tile)
        float s[4][4] = {};
        #pragma unroll 4
        for (int d = 0; d < 64; d++) {
            float a[4], bb[4];
            #pragma unroll
            for (int i = 0; i < 4; i++) a[i]  = Qs[(4 * ty + i) * FLD + d];
            #pragma unroll
            for (int j = 0; j < 4; j++) bb[j] = Ks[(4 * tx + j) * FLD + d];
            #pragma unroll
            for (int i = 0; i < 4; i++)
                #pragma unroll
                for (int j = 0; j < 4; j++)
                    s[i][j] = fmaf(a[i], bb[j], s[i][j]);
        }

        // online softmax update (rows owned by the 16 threads sharing ty)
        #pragma unroll
        for (int i = 0; i < 4; i++) {
            float mt = -1e30f;
            #pragma unroll
            for (int j = 0; j < 4; j++) {
                s[i][j] *= 0.125f;                      // 1/sqrt(64)
                mt = fmaxf(mt, s[i][j]);
            }
            #pragma unroll
            for (int off = 8; off > 0; off >>= 1)
                mt = fmaxf(mt, __shfl_xor_sync(0xffffffffu, mt, off));
            float mnew  = fmaxf(mrow[i], mt);
            float alpha = __expf(mrow[i] - mnew);
            float rs = 0.f;
            #pragma unroll
            for (int j = 0; j < 4; j++) {
                s[i][j] = __expf(s[i][j] - mnew);
                rs += s[i][j];
            }
            #pragma unroll
            for (int off = 8; off > 0; off >>= 1)
                rs += __shfl_xor_sync(0xffffffffu, rs, off);
            lrow[i] = lrow[i] * alpha + rs;
            mrow[i] = mnew;
            #pragma unroll
            for (int n = 0; n < 4; n++) o[i][n] *= alpha;
        }
        __syncthreads();     // everyone done reading Ks

        // stash P into the K buffer
        #pragma unroll
        for (int i = 0; i < 4; i++)
            #pragma unroll
            for (int j = 0; j < 4; j++)
                Ks[(4 * ty + i) * FLD + 4 * tx + j] = s[i][j];
        __syncthreads();

        // O += P * V
        #pragma unroll 4
        for (int j2 = 0; j2 < 64; j2++) {
            float pa[4], vb[4];
            #pragma unroll
            for (int i = 0; i < 4; i++) pa[i] = Ks[(4 * ty + i) * FLD + j2];
            #pragma unroll
            for (int n = 0; n < 4; n++) vb[n] = Vs[j2 * FLD + 4 * tx + n];
            #pragma unroll
            for (int i = 0; i < 4; i++)
                #pragma unroll
                for (int n = 0; n < 4; n++)
                    o[i][n] = fmaf(pa[i], vb[n], o[i][n]);
        }
        __syncthreads();     // before next tile overwrites Ks/Vs
    }

    #pragma unroll
    for (int i = 0; i < 4; i++) {
        float inv = 1.f / lrow[i];
        float* orow = O + base + (size_t)(q0 + 4 * ty + i) * DMODEL + 4 * tx;
        #pragma unroll
        for (int n = 0; n < 4; n++) orow[n] = o[i][n] * inv;
    }
}

// ---------------- add + LayerNorm -------------------------------------------
__global__ void add_ln_kernel(const float* __restrict__ x,
                              const float* __restrict__ y,
                              const float* __restrict__ gamma,
                              const float* __restrict__ beta,
                              float* __restrict__ out) {
    const int row = blockIdx.x;
    const int tid = threadIdx.x;
    const float* xr = x + (size_t)row * DMODEL;
    const float* yr = y + (size_t)row * DMODEL;
    float* orow = out + (size_t)row * DMODEL;

    float v[4], s = 0.f, ss = 0.f;
    #pragma unroll
    for (int j = 0; j < 4; j++) {
        int c = tid + j * 256;
        v[j] = xr[c] + yr[c];
        s  += v[j];
        ss += v[j] * v[j];
    }
    // block reduce (256 threads = 8 warps)
    __shared__ float rs[8], rss[8], bc[2];
    #pragma unroll
    for (int off = 16; off > 0; off >>= 1) {
        s  += __shfl_xor_sync(0xffffffffu, s,  off);
        ss += __shfl_xor_sync(0xffffffffu, ss, off);
    }
    if ((tid & 31) == 0) { rs[tid >> 5] = s; rss[tid >> 5] = ss; }
    __syncthreads();
    if (tid == 0) {
        float ts = 0.f, tss = 0.f;
        #pragma unroll
        for (int w = 0; w < 8; w++) { ts += rs[w]; tss += rss[w]; }
        float mu  = ts * (1.f / DMODEL);
        float var = tss * (1.f / DMODEL) - mu * mu;
        bc[0] = mu;
        bc[1] = rsqrtf(var + 1e-5f);
    }
    __syncthreads();
    float mu = bc[0], rstd = bc[1];
    #pragma unroll
    for (int j = 0; j < 4; j++) {
        int c = tid + j * 256;
        orow[c] = (v[j] - mu) * rstd * gamma[c] + beta[c];
    }
}

// ---------------- exact GELU (in place) -------------------------------------
__global__ void gelu_kernel(float* __restrict__ a, int n) {
    int i = blockIdx.x * blockDim.x + threadIdx.x;
    int stride = gridDim.x * blockDim.x;
    for (; i < n; i += stride) {
        float x = a[i];
        a[i] = 0.5f * x * (1.f + erff(x * 0.70710678118654752f));
    }
}

// ---------------- launch ----------------------------------------------------
extern "C" void kernel_launch(void* const* d_in, const int* in_sizes, int n_in,
                              void* d_out, int out_size) {
    const float* x  = (const float*)d_in[0];
    const float* Wq = (const float*)d_in[1];
    const float* Wk = (const float*)d_in[2];
    const float* Wv = (const float*)d_in[3];
    const float* Wo = (const float*)d_in[4];
    const float* W1 = (const float*)d_in[5];
    const float* W2 = (const float*)d_in[6];
    const float* g1 = (const float*)d_in[7];
    const float* b1 = (const float*)d_in[8];
    const float* g2 = (const float*)d_in[9];
    const float* b2 = (const float*)d_in[10];
    float* out = (float*)d_out;

    float *q, *k, *v, *attn, *proj, *x1, *ff;
    cudaGetSymbolAddress((void**)&q,    g_q);
    cudaGetSymbolAddress((void**)&k,    g_k);
    cudaGetSymbolAddress((void**)&v,    g_v);
    cudaGetSymbolAddress((void**)&attn, g_attn);
    cudaGetSymbolAddress((void**)&proj, g_proj);
    cudaGetSymbolAddress((void**)&x1,   g_x1);
    cudaGetSymbolAddress((void**)&ff,   g_ff);

    const int fa_smem = 3 * 64 * FLD * (int)sizeof(float);   // 49,920 B
    cudaFuncSetAttribute(flash_attn_kernel,
                         cudaFuncAttributeMaxDynamicSharedMemorySize, fa_smem);

    dim3 blk(256);

    // QKV projections: [4096,1024] x [1024,1024]^T
    dim3 gproj(DMODEL / 64, MTOK / 64);
    gemm_nt_kernel<<<gproj, blk>>>(x, Wq, q, MTOK, DMODEL, DMODEL);
    gemm_nt_kernel<<<gproj, blk>>>(x, Wk, k, MTOK, DMODEL, DMODEL);
    gemm_nt_kernel<<<gproj, blk>>>(x, Wv, v, MTOK, DMODEL, DMODEL);

    // attention
    dim3 gfa(S_LEN / 64, NHEADS, BATCH);
    flash_attn_kernel<<<gfa, blk, fa_smem>>>(q, k, v, attn);

    // output projection
    gemm_nt_kernel<<<gproj, blk>>>(attn, Wo, proj, MTOK, DMODEL, DMODEL);

    // add + LN 1
    add_ln_kernel<<<MTOK, blk>>>(x, proj, g1, b1, x1);

    // FFN up: [4096,1024] x [4096,1024]^T -> [4096,4096]
    dim3 gff1(DFF / 64, MTOK / 64);
    gemm_nt_kernel<<<gff1, blk>>>(x1, W1, ff, MTOK, DFF, DMODEL);

    // GELU
    gelu_kernel<<<4096, blk>>>(ff, MTOK * DFF);

    // FFN down: [4096,4096] x [1024,4096]^T -> [4096,1024]
    gemm_nt_kernel<<<gproj, blk>>>(ff, W2, proj, MTOK, DMODEL, DFF);

    // add + LN 2 -> output
    add_ln_kernel<<<MTOK, blk>>>(x1, proj, g2, b2, out);
}

// round 6
// speedup vs baseline: 2.2473x; 2.2473x over previous
#include <cuda_runtime.h>
#include <math.h>
#include <stdint.h>

#define S_LEN   2048
#define BATCH   2
#define DMODEL  1024
#define NHEADS  16
#define DK      64
#define DFF     4096
#define MTOK    (BATCH * S_LEN)   // 4096 tokens

// ---------------- scratch (device globals; no allocations allowed) ----------
__device__ float g_q   [MTOK * DMODEL];
__device__ float g_k   [MTOK * DMODEL];
__device__ float g_v   [MTOK * DMODEL];
__device__ float g_attn[MTOK * DMODEL];
__device__ float g_proj[MTOK * DMODEL];
__device__ float g_x1  [MTOK * DMODEL];
__device__ float g_x1r [MTOK * DMODEL];
__device__ float g_xr  [MTOK * DMODEL];
__device__ float g_ff  [MTOK * DFF];
__device__ float g_wq  [DMODEL * DMODEL];
__device__ float g_wk  [DMODEL * DMODEL];
__device__ float g_wv  [DMODEL * DMODEL];
__device__ float g_wo  [DMODEL * DMODEL];
__device__ float g_w1  [DFF * DMODEL];
__device__ float g_w2  [DMODEL * DFF];

// ---------------- helpers ----------------------------------------------------
__device__ __forceinline__ uint32_t sm_u32(const void* p) {
    uint32_t a;
    asm("{ .reg .u64 t; cvta.to.shared.u64 t, %1; cvt.u32.u64 %0, t; }"
        : "=r"(a) : "l"(p));
    return a;
}
__device__ __forceinline__ float rtf32(float x) {
    float r;
    asm("cvt.rna.tf32.f32 %0, %1;" : "=f"(r) : "f"(x));
    return r;
}
__device__ __forceinline__ void cp16(uint32_t dst, const void* src) {
    asm volatile("cp.async.cg.shared.global [%0], [%1], 16;"
                 :: "r"(dst), "l"(src) : "memory");
}
__device__ __forceinline__ void mma_tf32(float* d, const uint32_t* a, const uint32_t* b) {
    asm volatile(
        "mma.sync.aligned.m16n8k8.row.col.f32.tf32.tf32.f32 "
        "{%0,%1,%2,%3}, {%4,%5,%6,%7}, {%8,%9}, {%0,%1,%2,%3};"
        : "+f"(d[0]), "+f"(d[1]), "+f"(d[2]), "+f"(d[3])
        : "r"(a[0]), "r"(a[1]), "r"(a[2]), "r"(a[3]), "r"(b[0]), "r"(b[1]));
}

// ---------------- tf32 mma.sync GEMM: C[M,N] = A[M,K] * B[N,K]^T --------------
// 128x128 tile, BK=32, 3-stage cp.async pipeline, 256 threads (8 warps, 2x4),
// warp tile 64x32 via m16n8k8 (4 m-tiles x 4 n-tiles).
#define GSTAGES 3
#define GBM     128
#define GBN     128
#define GBK     32
#define GLD     36                          // padded smem stride (floats)
#define TILE_F  (128 * GLD)                 // floats per operand tile
#define STAGE_F (2 * TILE_F)                // A tile + B tile
#define GSMEM   (GSTAGES * STAGE_F * 4)     // 110,592 B

__device__ __forceinline__ void gemm_load_stage(
    float* sbase, int slot, const float* __restrict__ A, const float* __restrict__ B,
    int row0, int col0, int K, int chunk)
{
    const int tid = threadIdx.x;
    float* stage = sbase + slot * STAGE_F;
    uint32_t stage_u = sm_u32(stage);
    #pragma unroll
    for (int t = 0; t < 8; t++) {
        int idx = tid + t * 256;            // 0..2047 16B-chunks
        int isB = idx >> 10;
        int r   = (idx & 1023) >> 3;        // 0..127
        int c   = idx & 7;                  // 0..7 (x4 floats)
        const float* src = (isB ? (B + (size_t)(col0 + r) * K)
                                : (A + (size_t)(row0 + r) * K)) + chunk * GBK + c * 4;
        uint32_t dst = stage_u + (uint32_t)(isB * TILE_F + r * GLD + c * 4) * 4u;
        cp16(dst, src);
    }
}

__global__ void __launch_bounds__(256)
gemm_tc(const float* __restrict__ A, const float* __restrict__ B,
        float* __restrict__ C, int M, int N, int K)
{
    extern __shared__ float smem[];
    const int tid  = threadIdx.x;
    const int wid  = tid >> 5, lane = tid & 31;
    const int wm   = wid >> 2, wn = wid & 3;       // 2x4 warp grid
    const int row0 = blockIdx.y * GBM, col0 = blockIdx.x * GBN;
    const int lr   = lane >> 2, lc = lane & 3;

    float acc[4][4][4];
    #pragma unroll
    for (int i = 0; i < 4; i++)
        #pragma unroll
        for (int j = 0; j < 4; j++)
            #pragma unroll
            for (int q = 0; q < 4; q++) acc[i][j][q] = 0.f;

    const int nk = K / GBK;

    // prologue: stages 0,1
    gemm_load_stage(smem, 0, A, B, row0, col0, K, 0);
    asm volatile("cp.async.commit_group;" ::: "memory");
    gemm_load_stage(smem, 1, A, B, row0, col0, K, 1);
    asm volatile("cp.async.commit_group;" ::: "memory");

    for (int i = 0; i < nk; i++) {
        asm volatile("cp.async.wait_group 1;" ::: "memory");
        __syncthreads();

        // prefetch stage i+2 (uniform commit count: empty group on tail)
        if (i + 2 < nk)
            gemm_load_stage(smem, (i + 2) % GSTAGES, A, B, row0, col0, K, i + 2);
        asm volatile("cp.async.commit_group;" ::: "memory");

        // compute stage i
        const float* As = smem + (i % GSTAGES) * STAGE_F;
        const float* Bs = As + TILE_F;
        #pragma unroll
        for (int ks = 0; ks < 4; ks++) {       // 4 x k=8
            uint32_t af[4][4], bf[4][2];
            #pragma unroll
            for (int mt = 0; mt < 4; mt++) {
                const float* ap = As + (wm * 64 + mt * 16 + lr) * GLD + ks * 8 + lc;
                af[mt][0] = __float_as_uint(ap[0]);
                af[mt][1] = __float_as_uint(ap[8 * GLD]);
                af[mt][2] = __float_as_uint(ap[4]);
                af[mt][3] = __float_as_uint(ap[8 * GLD + 4]);
            }
            #pragma unroll
            for (int nt = 0; nt < 4; nt++) {
                const float* bp = Bs + (wn * 32 + nt * 8 + lr) * GLD + ks * 8 + lc;
                bf[nt][0] = __float_as_uint(bp[0]);
                bf[nt][1] = __float_as_uint(bp[4]);
            }
            #pragma unroll
            for (int mt = 0; mt < 4; mt++)
                #pragma unroll
                for (int nt = 0; nt < 4; nt++)
                    mma_tf32(acc[mt][nt], af[mt], bf[nt]);
        }
    }

    // epilogue: c0: (lr, 2*lc), c1: +1 col, c2/c3: row+8
    #pragma unroll
    for (int mt = 0; mt < 4; mt++) {
        #pragma unroll
        for (int nt = 0; nt < 4; nt++) {
            int r = row0 + wm * 64 + mt * 16 + lr;
            int c = col0 + wn * 32 + nt * 8 + 2 * lc;
            *(float2*)(C + (size_t)r * N + c) =
                make_float2(acc[mt][nt][0], acc[mt][nt][1]);
            *(float2*)(C + (size_t)(r + 8) * N + c) =
                make_float2(acc[mt][nt][2], acc[mt][nt][3]);
        }
    }
}

// ---------------- round-to-tf32 copy ----------------------------------------
__global__ void round_tf32_kernel(const float* __restrict__ in,
                                  float* __restrict__ out, int n4) {
    int i = blockIdx.x * blockDim.x + threadIdx.x;
    int stride = gridDim.x * blockDim.x;
    const float4* I = (const float4*)in;
    float4* O = (float4*)out;
    for (; i < n4; i += stride) {
        float4 v = I[i];
        v.x = rtf32(v.x); v.y = rtf32(v.y); v.z = rtf32(v.z); v.w = rtf32(v.w);
        O[i] = v;
    }
}

// ---------------- Flash attention (per (b,h), 64-query tiles) ----------------
#define FLD 65   // smem leading dim (bank-conflict pad)

__global__ void flash_attn_kernel(const float* __restrict__ Q,
                                  const float* __restrict__ K,
                                  const float* __restrict__ V,
                                  float* __restrict__ O) {
    extern __shared__ float sm[];
    float* Qs = sm;
    float* Ks = Qs + 64 * FLD;
    float* Vs = Ks + 64 * FLD;

    const int tid = threadIdx.x;
    const int tx  = tid & 15;
    const int ty  = tid >> 4;
    const int q0  = blockIdx.x * 64;
    const int h   = blockIdx.y;
    const int b   = blockIdx.z;
    const size_t base = (size_t)b * S_LEN * DMODEL + (size_t)h * DK;

    for (int i = tid; i < 64 * 16; i += 256) {
        int rr = i >> 4, cc = (i & 15) << 2;
        float4 v4 = *(const float4*)(Q + base + (size_t)(q0 + rr) * DMODEL + cc);
        Qs[rr * FLD + cc + 0] = v4.x; Qs[rr * FLD + cc + 1] = v4.y;
        Qs[rr * FLD + cc + 2] = v4.z; Qs[rr * FLD + cc + 3] = v4.w;
    }

    float mrow[4], lrow[4], o[4][4];
    #pragma unroll
    for (int i = 0; i < 4; i++) {
        mrow[i] = -1e30f; lrow[i] = 0.f;
        #pragma unroll
        for (int n = 0; n < 4; n++) o[i][n] = 0.f;
    }
    __syncthreads();

    for (int kt = 0; kt < S_LEN; kt += 64) {
        for (int i = tid; i < 64 * 16; i += 256) {
            int rr = i >> 4, cc = (i & 15) << 2;
            float4 k4 = *(const float4*)(K + base + (size_t)(kt + rr) * DMODEL + cc);
            float4 v4 = *(const float4*)(V + base + (size_t)(kt + rr) * DMODEL + cc);
            Ks[rr * FLD + cc + 0] = k4.x; Ks[rr * FLD + cc + 1] = k4.y;
            Ks[rr * FLD + cc + 2] = k4.z; Ks[rr * FLD + cc + 3] = k4.w;
            Vs[rr * FLD + cc + 0] = v4.x; Vs[rr * FLD + cc + 1] = v4.y;
            Vs[rr * FLD + cc + 2] = v4.z; Vs[rr * FLD + cc + 3] = v4.w;
        }
        __syncthreads();

        float s[4][4] = {};
        #pragma unroll 4
        for (int d = 0; d < 64; d++) {
            float a[4], bb[4];
            #pragma unroll
            for (int i = 0; i < 4; i++) a[i]  = Qs[(4 * ty + i) * FLD + d];
            #pragma unroll
            for (int j = 0; j < 4; j++) bb[j] = Ks[(4 * tx + j) * FLD + d];
            #pragma unroll
            for (int i = 0; i < 4; i++)
                #pragma unroll
                for (int j = 0; j < 4; j++)
                    s[i][j] = fmaf(a[i], bb[j], s[i][j]);
        }

        #pragma unroll
        for (int i = 0; i < 4; i++) {
            float mt = -1e30f;
            #pragma unroll
            for (int j = 0; j < 4; j++) {
                s[i][j] *= 0.125f;
                mt = fmaxf(mt, s[i][j]);
            }
            #pragma unroll
            for (int off = 8; off > 0; off >>= 1)
                mt = fmaxf(mt, __shfl_xor_sync(0xffffffffu, mt, off));
            float mnew  = fmaxf(mrow[i], mt);
            float alpha = __expf(mrow[i] - mnew);
            float rs = 0.f;
            #pragma unroll
            for (int j = 0; j < 4; j++) {
                s[i][j] = __expf(s[i][j] - mnew);
                rs += s[i][j];
            }
            #pragma unroll
            for (int off = 8; off > 0; off >>= 1)
                rs += __shfl_xor_sync(0xffffffffu, rs, off);
            lrow[i] = lrow[i] * alpha + rs;
            mrow[i] = mnew;
            #pragma unroll
            for (int n = 0; n < 4; n++) o[i][n] *= alpha;
        }
        __syncthreads();

        #pragma unroll
        for (int i = 0; i < 4; i++)
            #pragma unroll
            for (int j = 0; j < 4; j++)
                Ks[(4 * ty + i) * FLD + 4 * tx + j] = s[i][j];
        __syncthreads();

        #pragma unroll 4
        for (int j2 = 0; j2 < 64; j2++) {
            float pa[4], vb[4];
            #pragma unroll
            for (int i = 0; i < 4; i++) pa[i] = Ks[(4 * ty + i) * FLD + j2];
            #pragma unroll
            for (int n = 0; n < 4; n++) vb[n] = Vs[j2 * FLD + 4 * tx + n];
            #pragma unroll
            for (int i = 0; i < 4; i++)
                #pragma unroll
                for (int n = 0; n < 4; n++)
                    o[i][n] = fmaf(pa[i], vb[n], o[i][n]);
        }
        __syncthreads();
    }

    #pragma unroll
    for (int i = 0; i < 4; i++) {
        float inv = 1.f / lrow[i];
        float* orow = O + base + (size_t)(q0 + 4 * ty + i) * DMODEL + 4 * tx;
        #pragma unroll
        for (int n = 0; n < 4; n++) orow[n] = rtf32(o[i][n] * inv);   // tf32 for next GEMM
    }
}

// ---------------- add + LayerNorm (optional rounded second output) -----------
__global__ void add_ln_kernel(const float* __restrict__ x,
                              const float* __restrict__ y,
                              const float* __restrict__ gamma,
                              const float* __restrict__ beta,
                              float* __restrict__ out,
                              float* __restrict__ out_r) {
    const int row = blockIdx.x;
    const int tid = threadIdx.x;
    const float* xr = x + (size_t)row * DMODEL;
    const float* yr = y + (size_t)row * DMODEL;
    float* orow = out + (size_t)row * DMODEL;

    float v[4], s = 0.f, ss = 0.f;
    #pragma unroll
    for (int j = 0; j < 4; j++) {
        int c = tid + j * 256;
        v[j] = xr[c] + yr[c];
        s  += v[j];
        ss += v[j] * v[j];
    }
    __shared__ float rs[8], rss[8], bc[2];
    #pragma unroll
    for (int off = 16; off > 0; off >>= 1) {
        s  += __shfl_xor_sync(0xffffffffu, s,  off);
        ss += __shfl_xor_sync(0xffffffffu, ss, off);
    }
    if ((tid & 31) == 0) { rs[tid >> 5] = s; rss[tid >> 5] = ss; }
    __syncthreads();
    if (tid == 0) {
        float ts = 0.f, tss = 0.f;
        #pragma unroll
        for (int w = 0; w < 8; w++) { ts += rs[w]; tss += rss[w]; }
        float mu  = ts * (1.f / DMODEL);
        float var = tss * (1.f / DMODEL) - mu * mu;
        bc[0] = mu;
        bc[1] = rsqrtf(var + 1e-5f);
    }
    __syncthreads();
    float mu = bc[0], rstd = bc[1];
    #pragma unroll
    for (int j = 0; j < 4; j++) {
        int c = tid + j * 256;
        float o = (v[j] - mu) * rstd * gamma[c] + beta[c];
        orow[c] = o;
        if (out_r) out_r[(size_t)row * DMODEL + c] = rtf32(o);
    }
}

// ---------------- exact GELU (in place, rounds to tf32 for next GEMM) --------
__global__ void gelu_kernel(float* __restrict__ a, int n) {
    int i = blockIdx.x * blockDim.x + threadIdx.x;
    int stride = gridDim.x * blockDim.x;
    for (; i < n; i += stride) {
        float x = a[i];
        a[i] = rtf32(0.5f * x * (1.f + erff(x * 0.70710678118654752f)));
    }
}

// ---------------- launch ----------------------------------------------------
extern "C" void kernel_launch(void* const* d_in, const int* in_sizes, int n_in,
                              void* d_out, int out_size) {
    const float* x  = (const float*)d_in[0];
    const float* Wq = (const float*)d_in[1];
    const float* Wk = (const float*)d_in[2];
    const float* Wv = (const float*)d_in[3];
    const float* Wo = (const float*)d_in[4];
    const float* W1 = (const float*)d_in[5];
    const float* W2 = (const float*)d_in[6];
    const float* g1 = (const float*)d_in[7];
    const float* b1 = (const float*)d_in[8];
    const float* g2 = (const float*)d_in[9];
    const float* b2 = (const float*)d_in[10];
    float* out = (float*)d_out;

    float *q, *k, *v, *attn, *proj, *x1, *x1r, *xr, *ff;
    float *wq, *wk, *wv, *wo, *w1, *w2;
    cudaGetSymbolAddress((void**)&q,    g_q);
    cudaGetSymbolAddress((void**)&k,    g_k);
    cudaGetSymbolAddress((void**)&v,    g_v);
    cudaGetSymbolAddress((void**)&attn, g_attn);
    cudaGetSymbolAddress((void**)&proj, g_proj);
    cudaGetSymbolAddress((void**)&x1,   g_x1);
    cudaGetSymbolAddress((void**)&x1r,  g_x1r);
    cudaGetSymbolAddress((void**)&xr,   g_xr);
    cudaGetSymbolAddress((void**)&ff,   g_ff);
    cudaGetSymbolAddress((void**)&wq,   g_wq);
    cudaGetSymbolAddress((void**)&wk,   g_wk);
    cudaGetSymbolAddress((void**)&wv,   g_wv);
    cudaGetSymbolAddress((void**)&wo,   g_wo);
    cudaGetSymbolAddress((void**)&w1,   g_w1);
    cudaGetSymbolAddress((void**)&w2,   g_w2);

    const int fa_smem = 3 * 64 * FLD * (int)sizeof(float);
    cudaFuncSetAttribute(flash_attn_kernel,
                         cudaFuncAttributeMaxDynamicSharedMemorySize, fa_smem);
    cudaFuncSetAttribute(gemm_tc,
                         cudaFuncAttributeMaxDynamicSharedMemorySize, GSMEM);

    dim3 blk(256);

    // tf32 round-to-nearest copies of all GEMM operands
    round_tf32_kernel<<<512, 256>>>(x,  xr, MTOK * DMODEL / 4);
    round_tf32_kernel<<<512, 256>>>(Wq, wq, DMODEL * DMODEL / 4);
    round_tf32_kernel<<<512, 256>>>(Wk, wk, DMODEL * DMODEL / 4);
    round_tf32_kernel<<<512, 256>>>(Wv, wv, DMODEL * DMODEL / 4);
    round_tf32_kernel<<<512, 256>>>(Wo, wo, DMODEL * DMODEL / 4);
    round_tf32_kernel<<<512, 256>>>(W1, w1, DFF * DMODEL / 4);
    round_tf32_kernel<<<512, 256>>>(W2, w2, DMODEL * DFF / 4);

    // QKV projections (tf32 mma.sync)
    dim3 gproj(DMODEL / GBN, MTOK / GBM);   // (8, 32)
    gemm_tc<<<gproj, 256, GSMEM>>>(xr, wq, q, MTOK, DMODEL, DMODEL);
    gemm_tc<<<gproj, 256, GSMEM>>>(xr, wk, k, MTOK, DMODEL, DMODEL);
    gemm_tc<<<gproj, 256, GSMEM>>>(xr, wv, v, MTOK, DMODEL, DMODEL);

    // attention (fp32 SIMT, output rounded to tf32)
    dim3 gfa(S_LEN / 64, NHEADS, BATCH);
    flash_attn_kernel<<<gfa, blk, fa_smem>>>(q, k, v, attn);

    // output projection
    gemm_tc<<<gproj, 256, GSMEM>>>(attn, wo, proj, MTOK, DMODEL, DMODEL);

    // add + LN 1 (exact x1 + tf32 copy for FFN GEMM)
    add_ln_kernel<<<MTOK, blk>>>(x, proj, g1, b1, x1, x1r);

    // FFN up
    dim3 gff1(DFF / GBN, MTOK / GBM);       // (32, 32)
    gemm_tc<<<gff1, 256, GSMEM>>>(x1r, w1, ff, MTOK, DFF, DMODEL);

    // GELU (rounds to tf32 in place)
    gelu_kernel<<<4096, blk>>>(ff, MTOK * DFF);

    // FFN down (K = 4096)
    gemm_tc<<<gproj, 256, GSMEM>>>(ff, w2, proj, MTOK, DMODEL, DFF);

    // add + LN 2 -> output
    add_ln_kernel<<<MTOK, blk>>>(x1, proj, g2, b2, out, (float*)0);
}

// round 7
// speedup vs baseline: 2.6063x; 1.1598x over previous
#include <cuda_runtime.h>
#include <math.h>
#include <stdint.h>

#define S_LEN   2048
#define BATCH   2
#define DMODEL  1024
#define NHEADS  16
#define DK      64
#define DFF     4096
#define MTOK    (BATCH * S_LEN)   // 4096 tokens

// ---------------- scratch (device globals; no allocations allowed) ----------
__device__ float g_q   [MTOK * DMODEL];
__device__ float g_k   [MTOK * DMODEL];
__device__ float g_v   [MTOK * DMODEL];
__device__ float g_attn[MTOK * DMODEL];
__device__ float g_proj[MTOK * DMODEL];
__device__ float g_x1  [MTOK * DMODEL];
__device__ float g_x1r [MTOK * DMODEL];
__device__ float g_xr  [MTOK * DMODEL];
__device__ float g_ff  [MTOK * DFF];
__device__ float g_wq  [DMODEL * DMODEL];
__device__ float g_wk  [DMODEL * DMODEL];
__device__ float g_wv  [DMODEL * DMODEL];
__device__ float g_wo  [DMODEL * DMODEL];
__device__ float g_w1  [DFF * DMODEL];
__device__ float g_w2  [DMODEL * DFF];

// ---------------- helpers ----------------------------------------------------
__device__ __forceinline__ uint32_t sm_u32(const void* p) {
    uint32_t a;
    asm("{ .reg .u64 t; cvta.to.shared.u64 t, %1; cvt.u32.u64 %0, t; }"
        : "=r"(a) : "l"(p));
    return a;
}
__device__ __forceinline__ float rtf32(float x) {
    float r;
    asm("cvt.rna.tf32.f32 %0, %1;" : "=f"(r) : "f"(x));
    return r;
}
__device__ __forceinline__ void cp16(uint32_t dst, const void* src) {
    asm volatile("cp.async.cg.shared.global [%0], [%1], 16;"
                 :: "r"(dst), "l"(src) : "memory");
}
__device__ __forceinline__ void mma_tf32(float* d, const uint32_t* a, const uint32_t* b) {
    asm volatile(
        "mma.sync.aligned.m16n8k8.row.col.f32.tf32.tf32.f32 "
        "{%0,%1,%2,%3}, {%4,%5,%6,%7}, {%8,%9}, {%0,%1,%2,%3};"
        : "+f"(d[0]), "+f"(d[1]), "+f"(d[2]), "+f"(d[3])
        : "r"(a[0]), "r"(a[1]), "r"(a[2]), "r"(a[3]), "r"(b[0]), "r"(b[1]));
}

// ---------------- tf32 mma.sync GEMM: C[M,N] = A[M,K] * B[N,K]^T --------------
#define GSTAGES 3
#define GBM     128
#define GBN     128
#define GBK     32
#define GLD     36
#define TILE_F  (128 * GLD)
#define STAGE_F (2 * TILE_F)
#define GSMEM   (GSTAGES * STAGE_F * 4)     // 110,592 B

__device__ __forceinline__ void gemm_load_stage(
    float* sbase, int slot, const float* __restrict__ A, const float* __restrict__ B,
    int row0, int col0, int K, int chunk)
{
    const int tid = threadIdx.x;
    float* stage = sbase + slot * STAGE_F;
    uint32_t stage_u = sm_u32(stage);
    #pragma unroll
    for (int t = 0; t < 8; t++) {
        int idx = tid + t * 256;
        int isB = idx >> 10;
        int r   = (idx & 1023) >> 3;
        int c   = idx & 7;
        const float* src = (isB ? (B + (size_t)(col0 + r) * K)
                                : (A + (size_t)(row0 + r) * K)) + chunk * GBK + c * 4;
        uint32_t dst = stage_u + (uint32_t)(isB * TILE_F + r * GLD + c * 4) * 4u;
        cp16(dst, src);
    }
}

__global__ void __launch_bounds__(256)
gemm_tc(const float* __restrict__ A, const float* __restrict__ B,
        float* __restrict__ C, int M, int N, int K, int round_out)
{
    extern __shared__ float smem[];
    const int tid  = threadIdx.x;
    const int wid  = tid >> 5, lane = tid & 31;
    const int wm   = wid >> 2, wn = wid & 3;
    const int row0 = blockIdx.y * GBM, col0 = blockIdx.x * GBN;
    const int lr   = lane >> 2, lc = lane & 3;

    float acc[4][4][4];
    #pragma unroll
    for (int i = 0; i < 4; i++)
        #pragma unroll
        for (int j = 0; j < 4; j++)
            #pragma unroll
            for (int q = 0; q < 4; q++) acc[i][j][q] = 0.f;

    const int nk = K / GBK;

    gemm_load_stage(smem, 0, A, B, row0, col0, K, 0);
    asm volatile("cp.async.commit_group;" ::: "memory");
    gemm_load_stage(smem, 1, A, B, row0, col0, K, 1);
    asm volatile("cp.async.commit_group;" ::: "memory");

    for (int i = 0; i < nk; i++) {
        asm volatile("cp.async.wait_group 1;" ::: "memory");
        __syncthreads();

        if (i + 2 < nk)
            gemm_load_stage(smem, (i + 2) % GSTAGES, A, B, row0, col0, K, i + 2);
        asm volatile("cp.async.commit_group;" ::: "memory");

        const float* As = smem + (i % GSTAGES) * STAGE_F;
        const float* Bs = As + TILE_F;
        #pragma unroll
        for (int ks = 0; ks < 4; ks++) {
            uint32_t af[4][4], bf[4][2];
            #pragma unroll
            for (int mt = 0; mt < 4; mt++) {
                const float* ap = As + (wm * 64 + mt * 16 + lr) * GLD + ks * 8 + lc;
                af[mt][0] = __float_as_uint(ap[0]);
                af[mt][1] = __float_as_uint(ap[8 * GLD]);
                af[mt][2] = __float_as_uint(ap[4]);
                af[mt][3] = __float_as_uint(ap[8 * GLD + 4]);
            }
            #pragma unroll
            for (int nt = 0; nt < 4; nt++) {
                const float* bp = Bs + (wn * 32 + nt * 8 + lr) * GLD + ks * 8 + lc;
                bf[nt][0] = __float_as_uint(bp[0]);
                bf[nt][1] = __float_as_uint(bp[4]);
            }
            #pragma unroll
            for (int mt = 0; mt < 4; mt++)
                #pragma unroll
                for (int nt = 0; nt < 4; nt++)
                    mma_tf32(acc[mt][nt], af[mt], bf[nt]);
        }
    }

    #pragma unroll
    for (int mt = 0; mt < 4; mt++) {
        #pragma unroll
        for (int nt = 0; nt < 4; nt++) {
            int r = row0 + wm * 64 + mt * 16 + lr;
            int c = col0 + wn * 32 + nt * 8 + 2 * lc;
            float v0 = acc[mt][nt][0], v1 = acc[mt][nt][1];
            float v2 = acc[mt][nt][2], v3 = acc[mt][nt][3];
            if (round_out) {
                v0 = rtf32(v0); v1 = rtf32(v1); v2 = rtf32(v2); v3 = rtf32(v3);
            }
            *(float2*)(C + (size_t)r * N + c) = make_float2(v0, v1);
            *(float2*)(C + (size_t)(r + 8) * N + c) = make_float2(v2, v3);
        }
    }
}

// ---------------- round-to-tf32 copy ----------------------------------------
__global__ void round_tf32_kernel(const float* __restrict__ in,
                                  float* __restrict__ out, int n4) {
    int i = blockIdx.x * blockDim.x + threadIdx.x;
    int stride = gridDim.x * blockDim.x;
    const float4* I = (const float4*)in;
    float4* O = (float4*)out;
    for (; i < n4; i += stride) {
        float4 v = I[i];
        v.x = rtf32(v.x); v.y = rtf32(v.y); v.z = rtf32(v.z); v.w = rtf32(v.w);
        O[i] = v;
    }
}

// ---------------- Flash attention, tf32 mma.sync ------------------------------
// Br=128 queries/CTA, Bc=64 keys/tile, 8 warps; warp w owns query rows 16w..16w+15.
#define QLD 68
#define KLD 68
#define VLD 72
#define PLD 68
#define FA_Q  0
#define FA_K  (128 * QLD)                    // 8704
#define FA_V  (FA_K + 64 * KLD)              // 13056
#define FA_P  (FA_V + 64 * VLD)              // 17664
#define FA_TOT (FA_P + 128 * PLD)            // 26368 floats
#define FA_SMEM (FA_TOT * 4)                 // 105,472 B

__global__ void __launch_bounds__(256, 2)
flash_attn_tc(const float* __restrict__ Q, const float* __restrict__ K,
              const float* __restrict__ V, float* __restrict__ O) {
    extern __shared__ float sm[];
    float* Qs = sm + FA_Q;
    float* Ks = sm + FA_K;
    float* Vs = sm + FA_V;
    float* Ps = sm + FA_P;

    const int tid  = threadIdx.x;
    const int wid  = tid >> 5, lane = tid & 31;
    const int lr   = lane >> 2, lc = lane & 3;
    const int q0   = blockIdx.x * 128;
    const int h    = blockIdx.y;
    const int b    = blockIdx.z;
    const size_t base = (size_t)b * S_LEN * DMODEL + (size_t)h * DK;
    const int m0 = wid * 16;

    // load Q tile 128x64 (padded)
    #pragma unroll
    for (int t = 0; t < 8; t++) {
        int idx = tid + t * 256;
        int r = idx >> 4, c = idx & 15;
        *(float4*)&Qs[r * QLD + c * 4] =
            *(const float4*)(Q + base + (size_t)(q0 + r) * DMODEL + c * 4);
    }

    float m_st[2] = {-1e30f, -1e30f};
    float l_st[2] = {0.f, 0.f};
    float o[8][4];
    #pragma unroll
    for (int nt = 0; nt < 8; nt++)
        #pragma unroll
        for (int q = 0; q < 4; q++) o[nt][q] = 0.f;

    __syncthreads();

    const uint32_t Ks_u = sm_u32(Ks), Vs_u = sm_u32(Vs);

    for (int kt = 0; kt < S_LEN / 64; kt++) {
        // load K,V tiles (64x64 each) via cp.async
        #pragma unroll
        for (int t = 0; t < 4; t++) {
            int idx = tid + t * 256;
            int r = idx >> 4, c = idx & 15;
            const float* ks = K + base + (size_t)(kt * 64 + r) * DMODEL + c * 4;
            const float* vs = V + base + (size_t)(kt * 64 + r) * DMODEL + c * 4;
            cp16(Ks_u + (uint32_t)(r * KLD + c * 4) * 4u, ks);
            cp16(Vs_u + (uint32_t)(r * VLD + c * 4) * 4u, vs);
        }
        asm volatile("cp.async.commit_group;" ::: "memory");
        asm volatile("cp.async.wait_group 0;" ::: "memory");
        __syncthreads();

        // S = Q K^T  (warp: 16 x 64)
        float s[8][4];
        #pragma unroll
        for (int nt = 0; nt < 8; nt++)
            #pragma unroll
            for (int q = 0; q < 4; q++) s[nt][q] = 0.f;

        #pragma unroll
        for (int ks = 0; ks < 8; ks++) {
            uint32_t af[4];
            const float* ap = Qs + (m0 + lr) * QLD + ks * 8 + lc;
            af[0] = __float_as_uint(ap[0]);
            af[1] = __float_as_uint(ap[8 * QLD]);
            af[2] = __float_as_uint(ap[4]);
            af[3] = __float_as_uint(ap[8 * QLD + 4]);
            #pragma unroll
            for (int nt = 0; nt < 8; nt++) {
                uint32_t bf[2];
                const float* bp = Ks + (nt * 8 + lr) * KLD + ks * 8 + lc;
                bf[0] = __float_as_uint(bp[0]);
                bf[1] = __float_as_uint(bp[4]);
                mma_tf32(s[nt], af, bf);
            }
        }

        // online softmax on two rows (lr, lr+8)
        float mx0 = -1e30f, mx1 = -1e30f;
        #pragma unroll
        for (int nt = 0; nt < 8; nt++) {
            s[nt][0] *= 0.125f; s[nt][1] *= 0.125f;
            s[nt][2] *= 0.125f; s[nt][3] *= 0.125f;
            mx0 = fmaxf(mx0, fmaxf(s[nt][0], s[nt][1]));
            mx1 = fmaxf(mx1, fmaxf(s[nt][2], s[nt][3]));
        }
        mx0 = fmaxf(mx0, __shfl_xor_sync(0xffffffffu, mx0, 1));
        mx0 = fmaxf(mx0, __shfl_xor_sync(0xffffffffu, mx0, 2));
        mx1 = fmaxf(mx1, __shfl_xor_sync(0xffffffffu, mx1, 1));
        mx1 = fmaxf(mx1, __shfl_xor_sync(0xffffffffu, mx1, 2));

        float mn0 = fmaxf(m_st[0], mx0), mn1 = fmaxf(m_st[1], mx1);
        float al0 = __expf(m_st[0] - mn0), al1 = __expf(m_st[1] - mn1);
        float sum0 = 0.f, sum1 = 0.f;
        #pragma unroll
        for (int nt = 0; nt < 8; nt++) {
            s[nt][0] = __expf(s[nt][0] - mn0); sum0 += s[nt][0];
            s[nt][1] = __expf(s[nt][1] - mn0); sum0 += s[nt][1];
            s[nt][2] = __expf(s[nt][2] - mn1); sum1 += s[nt][2];
            s[nt][3] = __expf(s[nt][3] - mn1); sum1 += s[nt][3];
        }
        sum0 += __shfl_xor_sync(0xffffffffu, sum0, 1);
        sum0 += __shfl_xor_sync(0xffffffffu, sum0, 2);
        sum1 += __shfl_xor_sync(0xffffffffu, sum1, 1);
        sum1 += __shfl_xor_sync(0xffffffffu, sum1, 2);

        l_st[0] = l_st[0] * al0 + sum0;  m_st[0] = mn0;
        l_st[1] = l_st[1] * al1 + sum1;  m_st[1] = mn1;
        #pragma unroll
        for (int nt = 0; nt < 8; nt++) {
            o[nt][0] *= al0; o[nt][1] *= al0;
            o[nt][2] *= al1; o[nt][3] *= al1;
        }

        // write P (tf32-rounded) to warp-private smem region
        #pragma unroll
        for (int nt = 0; nt < 8; nt++) {
            *(float2*)&Ps[(m0 + lr) * PLD + nt * 8 + 2 * lc] =
                make_float2(rtf32(s[nt][0]), rtf32(s[nt][1]));
            *(float2*)&Ps[(m0 + lr + 8) * PLD + nt * 8 + 2 * lc] =
                make_float2(rtf32(s[nt][2]), rtf32(s[nt][3]));
        }
        __syncwarp();

        // O += P V   (warp: 16 x 64, k = 64)
        #pragma unroll
        for (int kc = 0; kc < 8; kc++) {
            uint32_t af[4];
            const float* ap = Ps + (m0 + lr) * PLD + kc * 8 + lc;
            af[0] = __float_as_uint(ap[0]);
            af[1] = __float_as_uint(ap[8 * PLD]);
            af[2] = __float_as_uint(ap[4]);
            af[3] = __float_as_uint(ap[8 * PLD + 4]);
            #pragma unroll
            for (int nt = 0; nt < 8; nt++) {
                uint32_t bf[2];
                const float* bp = Vs + (kc * 8 + lc) * VLD + nt * 8 + lr;
                bf[0] = __float_as_uint(bp[0]);
                bf[1] = __float_as_uint(bp[4 * VLD]);
                mma_tf32(o[nt], af, bf);
            }
        }
        __syncthreads();   // protect K/V before next tile's cp.async
    }

    float inv0 = 1.f / l_st[0], inv1 = 1.f / l_st[1];
    #pragma unroll
    for (int nt = 0; nt < 8; nt++) {
        int r = q0 + m0 + lr;
        int c = nt * 8 + 2 * lc;
        *(float2*)(O + base + (size_t)r * DMODEL + c) =
            make_float2(rtf32(o[nt][0] * inv0), rtf32(o[nt][1] * inv0));
        *(float2*)(O + base + (size_t)(r + 8) * DMODEL + c) =
            make_float2(rtf32(o[nt][2] * inv1), rtf32(o[nt][3] * inv1));
    }
}

// ---------------- add + LayerNorm (optional rounded second output) -----------
__global__ void add_ln_kernel(const float* __restrict__ x,
                              const float* __restrict__ y,
                              const float* __restrict__ gamma,
                              const float* __restrict__ beta,
                              float* __restrict__ out,
                              float* __restrict__ out_r) {
    const int row = blockIdx.x;
    const int tid = threadIdx.x;
    const float* xr = x + (size_t)row * DMODEL;
    const float* yr = y + (size_t)row * DMODEL;
    float* orow = out + (size_t)row * DMODEL;

    float v[4], s = 0.f, ss = 0.f;
    #pragma unroll
    for (int j = 0; j < 4; j++) {
        int c = tid + j * 256;
        v[j] = xr[c] + yr[c];
        s  += v[j];
        ss += v[j] * v[j];
    }
    __shared__ float rs[8], rss[8], bc[2];
    #pragma unroll
    for (int off = 16; off > 0; off >>= 1) {
        s  += __shfl_xor_sync(0xffffffffu, s,  off);
        ss += __shfl_xor_sync(0xffffffffu, ss, off);
    }
    if ((tid & 31) == 0) { rs[tid >> 5] = s; rss[tid >> 5] = ss; }
    __syncthreads();
    if (tid == 0) {
        float ts = 0.f, tss = 0.f;
        #pragma unroll
        for (int w = 0; w < 8; w++) { ts += rs[w]; tss += rss[w]; }
        float mu  = ts * (1.f / DMODEL);
        float var = tss * (1.f / DMODEL) - mu * mu;
        bc[0] = mu;
        bc[1] = rsqrtf(var + 1e-5f);
    }
    __syncthreads();
    float mu = bc[0], rstd = bc[1];
    #pragma unroll
    for (int j = 0; j < 4; j++) {
        int c = tid + j * 256;
        float o = (v[j] - mu) * rstd * gamma[c] + beta[c];
        orow[c] = o;
        if (out_r) out_r[(size_t)row * DMODEL + c] = rtf32(o);
    }
}

// ---------------- exact GELU (in place, rounds to tf32 for next GEMM) --------
__global__ void gelu_kernel(float* __restrict__ a, int n) {
    int i = blockIdx.x * blockDim.x + threadIdx.x;
    int stride = gridDim.x * blockDim.x;
    for (; i < n; i += stride) {
        float x = a[i];
        a[i] = rtf32(0.5f * x * (1.f + erff(x * 0.70710678118654752f)));
    }
}

// ---------------- launch ----------------------------------------------------
extern "C" void kernel_launch(void* const* d_in, const int* in_sizes, int n_in,
                              void* d_out, int out_size) {
    const float* x  = (const float*)d_in[0];
    const float* Wq = (const float*)d_in[1];
    const float* Wk = (const float*)d_in[2];
    const float* Wv = (const float*)d_in[3];
    const float* Wo = (const float*)d_in[4];
    const float* W1 = (const float*)d_in[5];
    const float* W2 = (const float*)d_in[6];
    const float* g1 = (const float*)d_in[7];
    const float* b1 = (const float*)d_in[8];
    const float* g2 = (const float*)d_in[9];
    const float* b2 = (const float*)d_in[10];
    float* out = (float*)d_out;

    float *q, *k, *v, *attn, *proj, *x1, *x1r, *xr, *ff;
    float *wq, *wk, *wv, *wo, *w1, *w2;
    cudaGetSymbolAddress((void**)&q,    g_q);
    cudaGetSymbolAddress((void**)&k,    g_k);
    cudaGetSymbolAddress((void**)&v,    g_v);
    cudaGetSymbolAddress((void**)&attn, g_attn);
    cudaGetSymbolAddress((void**)&proj, g_proj);
    cudaGetSymbolAddress((void**)&x1,   g_x1);
    cudaGetSymbolAddress((void**)&x1r,  g_x1r);
    cudaGetSymbolAddress((void**)&xr,   g_xr);
    cudaGetSymbolAddress((void**)&ff,   g_ff);
    cudaGetSymbolAddress((void**)&wq,   g_wq);
    cudaGetSymbolAddress((void**)&wk,   g_wk);
    cudaGetSymbolAddress((void**)&wv,   g_wv);
    cudaGetSymbolAddress((void**)&wo,   g_wo);
    cudaGetSymbolAddress((void**)&w1,   g_w1);
    cudaGetSymbolAddress((void**)&w2,   g_w2);

    cudaFuncSetAttribute(flash_attn_tc,
                         cudaFuncAttributeMaxDynamicSharedMemorySize, FA_SMEM);
    cudaFuncSetAttribute(gemm_tc,
                         cudaFuncAttributeMaxDynamicSharedMemorySize, GSMEM);

    dim3 blk(256);

    // tf32 round-to-nearest copies of all GEMM operands
    round_tf32_kernel<<<512, 256>>>(x,  xr, MTOK * DMODEL / 4);
    round_tf32_kernel<<<512, 256>>>(Wq, wq, DMODEL * DMODEL / 4);
    round_tf32_kernel<<<512, 256>>>(Wk, wk, DMODEL * DMODEL / 4);
    round_tf32_kernel<<<512, 256>>>(Wv, wv, DMODEL * DMODEL / 4);
    round_tf32_kernel<<<512, 256>>>(Wo, wo, DMODEL * DMODEL / 4);
    round_tf32_kernel<<<512, 256>>>(W1, w1, DFF * DMODEL / 4);
    round_tf32_kernel<<<512, 256>>>(W2, w2, DMODEL * DFF / 4);

    // QKV projections (tf32 mma.sync) — outputs rounded for the attention MMAs
    dim3 gproj(DMODEL / GBN, MTOK / GBM);   // (8, 32)
    gemm_tc<<<gproj, 256, GSMEM>>>(xr, wq, q, MTOK, DMODEL, DMODEL, 1);
    gemm_tc<<<gproj, 256, GSMEM>>>(xr, wk, k, MTOK, DMODEL, DMODEL, 1);
    gemm_tc<<<gproj, 256, GSMEM>>>(xr, wv, v, MTOK, DMODEL, DMODEL, 1);

    // attention (tf32 mma.sync flash)
    dim3 gfa(S_LEN / 128, NHEADS, BATCH);   // (16, 16, 2)
    flash_attn_tc<<<gfa, blk, FA_SMEM>>>(q, k, v, attn);

    // output projection
    gemm_tc<<<gproj, 256, GSMEM>>>(attn, wo, proj, MTOK, DMODEL, DMODEL, 0);

    // add + LN 1 (exact x1 + tf32 copy for FFN GEMM)
    add_ln_kernel<<<MTOK, blk>>>(x, proj, g1, b1, x1, x1r);

    // FFN up
    dim3 gff1(DFF / GBN, MTOK / GBM);       // (32, 32)
    gemm_tc<<<gff1, 256, GSMEM>>>(x1r, w1, ff, MTOK, DFF, DMODEL, 0);

    // GELU (rounds to tf32 in place)
    gelu_kernel<<<4096, blk>>>(ff, MTOK * DFF);

    // FFN down (K = 4096)
    gemm_tc<<<gproj, 256, GSMEM>>>(ff, w2, proj, MTOK, DMODEL, DFF, 0);

    // add + LN 2 -> output
    add_ln_kernel<<<MTOK, blk>>>(x1, proj, g2, b2, out, (float*)0);
}